// round 2
// baseline (speedup 1.0000x reference)
#include <cuda_runtime.h>
#include <cstdint>
#include <cstddef>

// Problem dims (fixed for this problem instance)
#define TT     4
#define BATCH  8
#define NTOK   1024
#define CDIM   768
#define HDIM   3072
#define NHEAD  8
#define DHEAD  96
#define WIN    8
#define NWIN   128
#define BNALL  (BATCH*NTOK)          // 8192 (b,n) rows; full M = TT*BNALL = 32768

// ---------------------------------------------------------------------------
// Scratch (static device globals — allocation-free per harness rules)
// ---------------------------------------------------------------------------
__device__ __align__(16) unsigned char g_qkv[(size_t)TT*BATCH*NTOK*3*CDIM]; // 75.5 MB spikes {0,1}
__device__ __align__(16) unsigned char g_osp[(size_t)TT*BATCH*NTOK*CDIM];   // 25.2 MB attn spikes
__device__ __align__(16) float         g_x1 [(size_t)TT*BATCH*NTOK*CDIM];   // 100.7 MB  x + proj
__device__ __align__(16) unsigned char g_h  [(size_t)TT*BATCH*NTOK*HDIM];   // 100.7 MB  f1 spikes

// ---------------------------------------------------------------------------
// f32x2 packed-FMA helpers (Blackwell: FFMA-3reg is rt=2/SMSP; f32x2 doubles it)
// Bitwise identical per-lane to scalar fp32 FMA.
// ---------------------------------------------------------------------------
__device__ __forceinline__ unsigned long long pack2(float x){
    unsigned long long r;
    asm("mov.b64 %0, {%1, %1};" : "=l"(r) : "f"(x));
    return r;
}
__device__ __forceinline__ void fma2(unsigned long long &d,
                                     unsigned long long a, unsigned long long b){
    asm("fma.rn.f32x2 %0, %1, %2, %0;" : "+l"(d) : "l"(a), "l"(b));
}
__device__ __forceinline__ float2 unpack2(unsigned long long v){
    float2 r;
    asm("mov.b64 {%0, %1}, %2;" : "=f"(r.x), "=f"(r.y) : "l"(v));
    return r;
}

// ---------------------------------------------------------------------------
// Fused GEMM + BN-affine + LIF kernel.
//   A: [TT*BNALL, K]  (float or u8 spikes),  row index = t*BNALL + bn
//   W: [OCdim, K] row-major  (y[.,o] = sum_c A[.,c]*W[o,c])
//   y = (acc + Bb[o]) * Sc[o] + Sh[o]; LIF over t (tau=2, hard reset, vth)
//   ADD_RES=false : write spike (u8) to Outp[(t*BNALL+bn)*OCtot + ocBase + oc]
//   ADD_RES=true  : write Res[idx] + spike (float) to Outp[idx]
// Tile: 32 bn x 128 oc x 4 t per block, 256 threads, KT=16.
// Per-thread: 2 bn x 8 oc x 4 t, accumulators packed f32x2 over oc pairs.
// ---------------------------------------------------------------------------
template<bool AU8, bool ADD_RES>
__global__ __launch_bounds__(256, 2)
void gemm_lif_kernel(const void* __restrict__ Ap,
                     const float* __restrict__ W,
                     const float* __restrict__ Bb,
                     const float* __restrict__ Sc,
                     const float* __restrict__ Sh,
                     void* __restrict__ Outp,
                     const float* __restrict__ Res,
                     int K, int OCtot, int ocBase, float vth)
{
    const int tid = threadIdx.x;
    const int ocT = tid & 15;        // 16 threads over oc, 8 each
    const int bnT = tid >> 4;        // 16 threads over bn, 2 each
    const int bn0 = blockIdx.y * 32;
    const int oc0 = blockIdx.x * 128;

    __shared__ float As[16][4][34];  // [k][t][bn] (+pad)
    __shared__ float Bs[16][128];    // [k][oc]

    unsigned long long acc[4][2][4]; // [t][bn_i][oc_pair]
    #pragma unroll
    for (int t=0;t<4;t++)
        #pragma unroll
        for (int i=0;i<2;i++)
            #pragma unroll
            for (int j=0;j<4;j++) acc[t][i][j] = 0ull;

    const int nk = K >> 4;

    float4 aP[2]; uint4 uP; float4 bP[2];

    auto loadTile = [&](int kt){
        const int k0 = kt * 16;
        if constexpr (AU8){
            if (tid < 128){
                const int t = tid >> 5, bn = tid & 31;
                uP = *reinterpret_cast<const uint4*>(
                    (const unsigned char*)Ap + (size_t)(t*BNALL + bn0 + bn)*K + k0);
            }
        } else {
            #pragma unroll
            for (int r=0;r<2;r++){
                const int v = tid*2 + r;
                const int t = v >> 7, bn = (v >> 2) & 31, kv = v & 3;
                aP[r] = *reinterpret_cast<const float4*>(
                    (const float*)Ap + (size_t)(t*BNALL + bn0 + bn)*K + k0 + kv*4);
            }
        }
        #pragma unroll
        for (int r=0;r<2;r++){
            const int v = tid*2 + r;
            const int oc = v >> 2, kv = v & 3;
            bP[r] = *reinterpret_cast<const float4*>(
                W + (size_t)(oc0 + oc)*K + k0 + kv*4);
        }
    };

    auto storeTile = [&](){
        if constexpr (AU8){
            if (tid < 128){
                const int t = tid >> 5, bn = tid & 31;
                unsigned int wv[4] = {uP.x, uP.y, uP.z, uP.w};
                #pragma unroll
                for (int k=0;k<16;k++)
                    As[k][t][bn] = (float)((wv[k>>2] >> ((k&3)*8)) & 255u);
            }
        } else {
            #pragma unroll
            for (int r=0;r<2;r++){
                const int v = tid*2 + r;
                const int t = v >> 7, bn = (v >> 2) & 31, kv = v & 3;
                As[kv*4+0][t][bn] = aP[r].x;
                As[kv*4+1][t][bn] = aP[r].y;
                As[kv*4+2][t][bn] = aP[r].z;
                As[kv*4+3][t][bn] = aP[r].w;
            }
        }
        #pragma unroll
        for (int r=0;r<2;r++){
            const int v = tid*2 + r;
            const int oc = v >> 2, kv = v & 3;
            Bs[kv*4+0][oc] = bP[r].x;
            Bs[kv*4+1][oc] = bP[r].y;
            Bs[kv*4+2][oc] = bP[r].z;
            Bs[kv*4+3][oc] = bP[r].w;
        }
    };

    loadTile(0);
    for (int kt = 0; kt < nk; kt++){
        storeTile();
        __syncthreads();
        if (kt + 1 < nk) loadTile(kt + 1);
        #pragma unroll
        for (int k=0;k<16;k++){
            unsigned long long b2[4];
            #pragma unroll
            for (int j=0;j<4;j++)
                b2[j] = *reinterpret_cast<const unsigned long long*>(&Bs[k][ocT*8 + j*2]);
            #pragma unroll
            for (int t=0;t<4;t++){
                const float2 av = *reinterpret_cast<const float2*>(&As[k][t][bnT*2]);
                const unsigned long long a0 = pack2(av.x);
                const unsigned long long a1 = pack2(av.y);
                #pragma unroll
                for (int j=0;j<4;j++){
                    fma2(acc[t][0][j], a0, b2[j]);
                    fma2(acc[t][1][j], a1, b2[j]);
                }
            }
        }
        __syncthreads();
    }

    // Epilogue: BN affine + LIF over t, then store
    #pragma unroll
    for (int i=0;i<2;i++){
        const int bng = bn0 + bnT*2 + i;
        #pragma unroll
        for (int j2=0;j2<4;j2++){
            const int ocA = oc0 + ocT*8 + j2*2;
            const float b0 = Bb[ocA],   b1 = Bb[ocA+1];
            const float s0 = Sc[ocA],   s1 = Sc[ocA+1];
            const float h0 = Sh[ocA],   h1 = Sh[ocA+1];
            float v0 = 0.f, v1 = 0.f;
            #pragma unroll
            for (int t=0;t<4;t++){
                const float2 y = unpack2(acc[t][i][j2]);
                float y0 = (y.x + b0) * s0 + h0;
                float y1 = (y.y + b1) * s1 + h1;
                v0 += (y0 - v0) * 0.5f;
                v1 += (y1 - v1) * 0.5f;
                const float sp0 = (v0 >= vth) ? 1.f : 0.f;
                const float sp1 = (v1 >= vth) ? 1.f : 0.f;
                const size_t idx = (size_t)(t*BNALL + bng)*OCtot + ocBase + ocA;
                if constexpr (ADD_RES){
                    ((float*)Outp)[idx]     = Res[idx]     + sp0;
                    ((float*)Outp)[idx + 1] = Res[idx + 1] + sp1;
                } else {
                    ((unsigned char*)Outp)[idx]     = (unsigned char)sp0;
                    ((unsigned char*)Outp)[idx + 1] = (unsigned char)sp1;
                }
                v0 *= (1.f - sp0);
                v1 *= (1.f - sp1);
            }
        }
    }
}

// ---------------------------------------------------------------------------
// Local attention on binary spikes + fused attn_lif (vth=0.5) over T.
// One block per (b, h, window). Windows of 8 queries attend to 16 keys
// (previous window + own window); first window masked to own 8.
// ---------------------------------------------------------------------------
__global__ __launch_bounds__(128)
void attn_kernel(const unsigned char* __restrict__ qkv,
                 unsigned char* __restrict__ osp)
{
    const int blk = blockIdx.x;
    const int nw = blk & (NWIN-1);
    const int h  = (blk >> 7) & (NHEAD-1);
    const int bb = blk >> 10;
    const int n0 = nw * WIN;
    const int tid = threadIdx.x;

    __shared__ float qs[8][96];
    __shared__ float ks[16][100];
    __shared__ float vs[16][100];
    __shared__ float p_sh[8][16];
    __shared__ float vst[768];

    for (int idx = tid; idx < 768; idx += 128) vst[idx] = 0.f;

    const int i_ = tid >> 4;   // query row 0..7
    const int j_ = tid & 15;   // key col 0..15
    const float SCALE = 0.10206207261596577f;  // 96^-0.5

    for (int t = 0; t < TT; t++){
        const int rowbase = (t*BATCH + bb) * NTOK;
        // load q window
        for (int idx = tid; idx < 8*96; idx += 128){
            const int i = idx / 96, d = idx - 96*i;
            qs[i][d] = (float)qkv[(size_t)(rowbase + n0 + i)*(3*CDIM) + h*DHEAD + d];
        }
        // load k, v windows (16 rows: prev 8 + own 8)
        for (int idx = tid; idx < 16*96; idx += 128){
            const int j = idx / 96, d = idx - 96*j;
            const int n = n0 - 8 + j;
            float kv = 0.f, vv = 0.f;
            if (n >= 0){
                const size_t base = (size_t)(rowbase + n)*(3*CDIM) + h*DHEAD + d;
                kv = (float)qkv[base + CDIM];
                vv = (float)qkv[base + 2*CDIM];
            }
            ks[j][d] = kv;
            vs[j][d] = vv;
        }
        __syncthreads();

        // sim[i][j] = scale * <q_i, k_j>  (dot of binaries = exact count)
        float cnt = 0.f;
        {
            const float4* q4 = reinterpret_cast<const float4*>(&qs[i_][0]);
            const float4* k4 = reinterpret_cast<const float4*>(&ks[j_][0]);
            #pragma unroll
            for (int c = 0; c < 24; c++){
                const float4 a = q4[c], b = k4[c];
                cnt += a.x*b.x + a.y*b.y + a.z*b.z + a.w*b.w;
            }
        }
        float sim = cnt * SCALE;
        if (nw == 0 && j_ < 8) sim = -3.402823466e+38f;   // mask lookback of first window

        // softmax over j within 16-lane groups
        float mx = sim;
        #pragma unroll
        for (int o = 8; o; o >>= 1) mx = fmaxf(mx, __shfl_xor_sync(0xffffffffu, mx, o));
        const float e = expf(sim - mx);
        float sm = e;
        #pragma unroll
        for (int o = 8; o; o >>= 1) sm += __shfl_xor_sync(0xffffffffu, sm, o);
        p_sh[i_][j_] = e / sm;
        __syncthreads();

        // out[i][d] = sum_j p[i][j] * v[j][d]; fused attn_lif (vth=0.5)
        for (int idx = tid; idx < 8*96; idx += 128){
            const int i = idx / 96, d = idx - 96*i;
            float o = 0.f;
            #pragma unroll
            for (int j = 0; j < 16; j++) o += p_sh[i][j] * vs[j][d];
            float v = vst[idx];
            v += (o - v) * 0.5f;
            const float sp = (v >= 0.5f) ? 1.f : 0.f;
            osp[(size_t)(rowbase + n0 + i)*CDIM + h*DHEAD + d] = (unsigned char)sp;
            vst[idx] = v * (1.f - sp);
        }
        __syncthreads();
    }
}

// ---------------------------------------------------------------------------
// Launch
// ---------------------------------------------------------------------------
extern "C" void kernel_launch(void* const* d_in, const int* in_sizes, int n_in,
                              void* d_out, int out_size)
{
    const float* x   = (const float*)d_in[0];
    const float* qw  = (const float*)d_in[1];
    const float* qb  = (const float*)d_in[2];
    const float* qs_ = (const float*)d_in[3];
    const float* qt  = (const float*)d_in[4];
    const float* kw  = (const float*)d_in[5];
    const float* kb  = (const float*)d_in[6];
    const float* ks_ = (const float*)d_in[7];
    const float* kt  = (const float*)d_in[8];
    const float* vw  = (const float*)d_in[9];
    const float* vb  = (const float*)d_in[10];
    const float* vs_ = (const float*)d_in[11];
    const float* vt  = (const float*)d_in[12];
    const float* pw  = (const float*)d_in[13];
    const float* pb  = (const float*)d_in[14];
    const float* ps  = (const float*)d_in[15];
    const float* pt  = (const float*)d_in[16];
    const float* f1w = (const float*)d_in[17];
    const float* f1b = (const float*)d_in[18];
    const float* f1s = (const float*)d_in[19];
    const float* f1t = (const float*)d_in[20];
    const float* f2w = (const float*)d_in[21];
    const float* f2b = (const float*)d_in[22];
    const float* f2s = (const float*)d_in[23];
    const float* f2t = (const float*)d_in[24];

    void *p_qkv, *p_osp, *p_x1, *p_h;
    cudaGetSymbolAddress(&p_qkv, g_qkv);
    cudaGetSymbolAddress(&p_osp, g_osp);
    cudaGetSymbolAddress(&p_x1,  g_x1);
    cudaGetSymbolAddress(&p_h,   g_h);

    const dim3 gC(CDIM/128, BNALL/32);   // (6, 256)
    const dim3 gH(HDIM/128, BNALL/32);   // (24, 256)

    // Q / K / V projections -> spikes into g_qkv (concat cols: q|k|v)
    gemm_lif_kernel<false,false><<<gC, 256>>>(x, qw, qb, qs_, qt, p_qkv, nullptr,
                                              CDIM, 3*CDIM, 0,       1.0f);
    gemm_lif_kernel<false,false><<<gC, 256>>>(x, kw, kb, ks_, kt, p_qkv, nullptr,
                                              CDIM, 3*CDIM, CDIM,    1.0f);
    gemm_lif_kernel<false,false><<<gC, 256>>>(x, vw, vb, vs_, vt, p_qkv, nullptr,
                                              CDIM, 3*CDIM, 2*CDIM,  1.0f);

    // Local attention + attn_lif -> spike u8
    attn_kernel<<<BATCH*NHEAD*NWIN, 128>>>((const unsigned char*)p_qkv,
                                           (unsigned char*)p_osp);

    // proj: spikes -> LIF spike, fused residual: x1 = x + spike
    gemm_lif_kernel<true,true><<<gC, 256>>>(p_osp, pw, pb, ps, pt, p_x1, x,
                                            CDIM, CDIM, 0, 1.0f);

    // f1: x1 -> h spikes (u8)
    gemm_lif_kernel<false,false><<<gH, 256>>>(p_x1, f1w, f1b, f1s, f1t, p_h, nullptr,
                                              CDIM, HDIM, 0, 1.0f);

    // f2: h spikes -> LIF spike, fused residual: out = x1 + spike
    gemm_lif_kernel<true,true><<<gC, 256>>>(p_h, f2w, f2b, f2s, f2t, d_out,
                                            (const float*)p_x1,
                                            HDIM, CDIM, 0, 1.0f);
}

// round 5
// speedup vs baseline: 2.8243x; 2.8243x over previous
#include <cuda_runtime.h>
#include <cuda_fp16.h>
#include <cstdint>
#include <cstddef>

#define TT 4
#define BATCH 8
#define NTOK 1024
#define CDIM 768
#define HDIM 3072
#define NHEAD 8
#define DHEAD 96
#define NWIN 128
#define BNALL (BATCH*NTOK)
#define MTOT  (TT*BNALL)
#define QKVC  (3*CDIM)

// ---------------- static scratch ----------------
__device__ __align__(128) float  g_y   [(size_t)MTOT*HDIM];
__device__ __align__(128) __half g_xs0 [(size_t)MTOT*CDIM];
__device__ __align__(128) __half g_xs1 [(size_t)MTOT*CDIM];
__device__ __align__(128) __half g_x1s0[(size_t)MTOT*CDIM];
__device__ __align__(128) __half g_x1s1[(size_t)MTOT*CDIM];
__device__ __align__(128) float  g_x1f [(size_t)MTOT*CDIM];
__device__ __align__(128) __half g_qkvs[(size_t)MTOT*QKVC];
__device__ __align__(128) __half g_osp [(size_t)MTOT*CDIM];
__device__ __align__(128) __half g_hs  [(size_t)MTOT*HDIM];
#define WTOT 7077888
__device__ __align__(128) __half g_w0[WTOT];
__device__ __align__(128) __half g_w1[WTOT];
#define WO_QKV 0
#define WO_P   1769472
#define WO_F1  2359296
#define WO_F2  4718592

// ---------------- helpers ----------------
__device__ __forceinline__ uint32_t s2u(const void* p){
    uint32_t a;
    asm("{ .reg .u64 t; cvta.to.shared.u64 t, %1; cvt.u32.u64 %0, t; }" : "=r"(a) : "l"(p));
    return a;
}
__device__ __forceinline__ void cpasync16(uint32_t s, const void* g){
    asm volatile("cp.async.cg.shared.global [%0], [%1], 16;"
                 :: "r"(s), "l"(__cvta_generic_to_global(g)) : "memory");
}
__device__ __forceinline__ void ldsm4(uint32_t* r, uint32_t a){
    asm volatile("ldmatrix.sync.aligned.m8n8.x4.shared.b16 {%0,%1,%2,%3}, [%4];"
        : "=r"(r[0]),"=r"(r[1]),"=r"(r[2]),"=r"(r[3]) : "r"(a));
}
__device__ __forceinline__ void mma16816(float* c, const uint32_t* a, const uint32_t* b){
    asm volatile("mma.sync.aligned.m16n8k16.row.col.f32.f16.f16.f32 "
        "{%0,%1,%2,%3}, {%4,%5,%6,%7}, {%8,%9}, {%0,%1,%2,%3};"
        : "+f"(c[0]),"+f"(c[1]),"+f"(c[2]),"+f"(c[3])
        : "r"(a[0]),"r"(a[1]),"r"(a[2]),"r"(a[3]), "r"(b[0]),"r"(b[1]));
}

// ---------------- GEMM: Y[m,n] = sum_seg sum_k A[m,k]*B[n,k] ----------------
struct GemmP {
    const __half* A[3]; const __half* B[3];
    int nseg, K; float* Y; int N;
};
#define STAGES 3
#define STGB 32768
#define GSMEM (STAGES*STGB)

__global__ __launch_bounds__(256) void gemm_mma(GemmP p)
{
    extern __shared__ char sm[];
    const uint32_t sb = s2u(sm);
    const int tid = threadIdx.x;
    const int m0 = blockIdx.y * 128, n0 = blockIdx.x * 128;
    const int kc = p.K >> 6;
    const int total = p.nseg * kc;

    auto issue = [&](int c){
        const int seg = c / kc, ck = c - seg*kc;
        const uint32_t stg = sb + (uint32_t)(c % STAGES) * STGB;
        const __half* Ag = p.A[seg] + (size_t)m0 * p.K + ck*64;
        const __half* Bg = p.B[seg] + (size_t)n0 * p.K + ck*64;
        #pragma unroll
        for (int i = 0; i < 4; i++){
            const int u = tid + i*256;            // 0..1023
            const int row = u >> 3, c16 = u & 7;  // 128 rows x 8 x 16B
            const uint32_t so = (uint32_t)(row*128 + ((c16 ^ (row & 7)) * 16));
            cpasync16(stg + so,         Ag + (size_t)row * p.K + c16*8);
            cpasync16(stg + 16384 + so, Bg + (size_t)row * p.K + c16*8);
        }
        asm volatile("cp.async.commit_group;" ::: "memory");
    };

    issue(0); issue(1); issue(2);

    float acc[4][4][4];
    #pragma unroll
    for (int a=0;a<4;a++)
        #pragma unroll
        for (int b=0;b<4;b++)
            #pragma unroll
            for (int q=0;q<4;q++) acc[a][b][q] = 0.f;

    const int lane = tid & 31, wid = tid >> 5, wm = wid & 1, wn = wid >> 1;
    const int arow = (lane & 7) + ((lane >> 3) & 1) * 8;
    const int a_u  = lane >> 4;
    const int brow = (lane & 7) + (lane >> 4) * 8;
    const int b_u  = (lane >> 3) & 1;
    const uint32_t aBase = sb + (uint32_t)((wm*64 + arow) * 128);
    const uint32_t bBase = sb + 16384 + (uint32_t)((wn*32 + brow) * 128);
    const int aX = arow & 7, bX = brow & 7;

    for (int c = 0; c < total; c++){
        asm volatile("cp.async.wait_group 2;" ::: "memory");
        __syncthreads();
        const uint32_t stg = (uint32_t)(c % STAGES) * STGB;
        #pragma unroll
        for (int ks = 0; ks < 4; ks++){
            uint32_t af[4][4], bf[4][2];
            #pragma unroll
            for (int mi = 0; mi < 4; mi++)
                ldsm4(af[mi], aBase + stg + (uint32_t)(mi*2048) +
                      (uint32_t)(((ks*2 + a_u) ^ aX) * 16));
            #pragma unroll
            for (int np = 0; np < 2; np++){
                uint32_t r[4];
                ldsm4(r, bBase + stg + (uint32_t)(np*2048) +
                      (uint32_t)(((ks*2 + b_u) ^ bX) * 16));
                bf[2*np][0] = r[0]; bf[2*np][1] = r[1];
                bf[2*np+1][0] = r[2]; bf[2*np+1][1] = r[3];
            }
            #pragma unroll
            for (int mi = 0; mi < 4; mi++)
                #pragma unroll
                for (int ni = 0; ni < 4; ni++)
                    mma16816(acc[mi][ni], af[mi], bf[ni]);
        }
        __syncthreads();
        if (c + STAGES < total) issue(c + STAGES);
        else asm volatile("cp.async.commit_group;" ::: "memory");
    }

    const int r0 = m0 + wm*64 + (lane >> 2);
    const int c0 = n0 + wn*32 + (lane & 3) * 2;
    #pragma unroll
    for (int mi = 0; mi < 4; mi++){
        #pragma unroll
        for (int ni = 0; ni < 4; ni++){
            float* y = p.Y + (size_t)(r0 + mi*16) * p.N + c0 + ni*8;
            *reinterpret_cast<float2*>(y) = make_float2(acc[mi][ni][0], acc[mi][ni][1]);
            *reinterpret_cast<float2*>(y + (size_t)8 * p.N) =
                make_float2(acc[mi][ni][2], acc[mi][ni][3]);
        }
    }
}

// ---------------- elementwise ----------------
__device__ __forceinline__ void dek2(float a, unsigned short& u0, unsigned short& u1){
    const __half h0 = __float2half_rn(a);
    const float r1 = a - __half2float(h0);
    const __half h1 = __float2half_rn(r1);
    u0 = __half_as_ushort(h0); u1 = __half_as_ushort(h1);
}

__global__ void split2_kernel(const float* __restrict__ src,
                              __half* __restrict__ d0, __half* __restrict__ d1,
                              long long n4)
{
    const long long i = (long long)blockIdx.x * blockDim.x + threadIdx.x;
    if (i >= n4) return;
    const float4 v = *reinterpret_cast<const float4*>(src + i*4);
    unsigned short a0,a1,b0,b1,c0,c1,e0,e1;
    dek2(v.x,a0,a1); dek2(v.y,b0,b1); dek2(v.z,c0,c1); dek2(v.w,e0,e1);
    *reinterpret_cast<uint2*>(d0 + i*4) =
        make_uint2((uint32_t)a0 | ((uint32_t)b0 << 16), (uint32_t)c0 | ((uint32_t)e0 << 16));
    *reinterpret_cast<uint2*>(d1 + i*4) =
        make_uint2((uint32_t)a1 | ((uint32_t)b1 << 16), (uint32_t)c1 | ((uint32_t)e1 << 16));
}

// BN + LIF -> fp16 spikes
__global__ void lif_plain(const float* __restrict__ Y, const float* __restrict__ Bb,
                          const float* __restrict__ Sc, const float* __restrict__ Sh,
                          __half* __restrict__ O, int OC, int ldY, int ybase,
                          int ldO, int obase)
{
    const long long i = (long long)blockIdx.x * blockDim.x + threadIdx.x;
    if (i >= (long long)BNALL * OC) return;
    const int oc = (int)(i % OC), bn = (int)(i / OC);
    const float b = Bb[oc], s = Sc[oc], h = Sh[oc];
    float v = 0.f;
    #pragma unroll
    for (int t = 0; t < TT; t++){
        const size_t r = (size_t)(t*BNALL + bn);
        const float z = (Y[r*ldY + ybase + oc] + b)*s + h;
        v += (z - v)*0.5f;
        const float sp = (v >= 1.f) ? 1.f : 0.f;
        O[r*ldO + obase + oc] = __float2half(sp);
        v *= (1.f - sp);
    }
}

// proj epilogue: BN+LIF, x1 = x + spike -> x1 float + 2-way split
__global__ void lif_proj(const float* __restrict__ Y, const float* __restrict__ Bb,
                         const float* __restrict__ Sc, const float* __restrict__ Sh,
                         const float* __restrict__ X, float* __restrict__ X1,
                         __half* __restrict__ d0, __half* __restrict__ d1)
{
    const long long i = (long long)blockIdx.x * blockDim.x + threadIdx.x;
    if (i >= (long long)BNALL * CDIM) return;
    const int oc = (int)(i % CDIM), bn = (int)(i / CDIM);
    const float b = Bb[oc], s = Sc[oc], h = Sh[oc];
    float v = 0.f;
    #pragma unroll
    for (int t = 0; t < TT; t++){
        const size_t idx = (size_t)(t*BNALL + bn)*CDIM + oc;
        const float z = (Y[idx] + b)*s + h;
        v += (z - v)*0.5f;
        const float sp = (v >= 1.f) ? 1.f : 0.f;
        const float x1 = X[idx] + sp;
        X1[idx] = x1;
        unsigned short u0,u1; dek2(x1,u0,u1);
        d0[idx] = __ushort_as_half(u0);
        d1[idx] = __ushort_as_half(u1);
        v *= (1.f - sp);
    }
}

// f2 epilogue: BN+LIF, out = x1 + spike
__global__ void lif_out(const float* __restrict__ Y, const float* __restrict__ Bb,
                        const float* __restrict__ Sc, const float* __restrict__ Sh,
                        const float* __restrict__ X1, float* __restrict__ Out)
{
    const long long i = (long long)blockIdx.x * blockDim.x + threadIdx.x;
    if (i >= (long long)BNALL * CDIM) return;
    const int oc = (int)(i % CDIM), bn = (int)(i / CDIM);
    const float b = Bb[oc], s = Sc[oc], h = Sh[oc];
    float v = 0.f;
    #pragma unroll
    for (int t = 0; t < TT; t++){
        const size_t idx = (size_t)(t*BNALL + bn)*CDIM + oc;
        const float z = (Y[idx] + b)*s + h;
        v += (z - v)*0.5f;
        const float sp = (v >= 1.f) ? 1.f : 0.f;
        Out[idx] = X1[idx] + sp;
        v *= (1.f - sp);
    }
}

// ---------------- local attention + attn_lif ----------------
__global__ __launch_bounds__(128)
void attn_kernel(const __half* __restrict__ qkv, __half* __restrict__ osp)
{
    const int blk = blockIdx.x;
    const int nw = blk & (NWIN-1);
    const int hh = (blk >> 7) & (NHEAD-1);
    const int bb = blk >> 10;
    const int n0 = nw * 8;
    const int tid = threadIdx.x;

    __shared__ float qs[8][96];
    __shared__ float ks[16][100];
    __shared__ float vs[16][100];
    __shared__ float ps[8][16];
    __shared__ float vst[768];
    for (int idx = tid; idx < 768; idx += 128) vst[idx] = 0.f;

    const int i_ = tid >> 4, j_ = tid & 15;
    const float SCALE = 0.10206207261596577f;

    for (int t = 0; t < TT; t++){
        const int rowbase = (t*BATCH + bb) * NTOK;
        for (int idx = tid; idx < 8*96; idx += 128){
            const int i = idx / 96, d = idx - 96*i;
            qs[i][d] = __half2float(qkv[(size_t)(rowbase + n0 + i)*QKVC + hh*DHEAD + d]);
        }
        for (int idx = tid; idx < 16*96; idx += 128){
            const int j = idx / 96, d = idx - 96*j;
            const int n = n0 - 8 + j;
            float kv = 0.f, vv = 0.f;
            if (n >= 0){
                const size_t base = (size_t)(rowbase + n)*QKVC + hh*DHEAD + d;
                kv = __half2float(qkv[base + CDIM]);
                vv = __half2float(qkv[base + 2*CDIM]);
            }
            ks[j][d] = kv; vs[j][d] = vv;
        }
        __syncthreads();

        float cnt = 0.f;
        {
            const float4* q4 = reinterpret_cast<const float4*>(&qs[i_][0]);
            const float4* k4 = reinterpret_cast<const float4*>(&ks[j_][0]);
            #pragma unroll
            for (int c = 0; c < 24; c++){
                const float4 a = q4[c], b = k4[c];
                cnt += a.x*b.x + a.y*b.y + a.z*b.z + a.w*b.w;
            }
        }
        float sim = cnt * SCALE;
        if (nw == 0 && j_ < 8) sim = -3.402823466e+38f;
        float mx = sim;
        #pragma unroll
        for (int o = 8; o; o >>= 1) mx = fmaxf(mx, __shfl_xor_sync(0xffffffffu, mx, o));
        const float e = expf(sim - mx);
        float smv = e;
        #pragma unroll
        for (int o = 8; o; o >>= 1) smv += __shfl_xor_sync(0xffffffffu, smv, o);
        ps[i_][j_] = e / smv;
        __syncthreads();

        for (int idx = tid; idx < 8*96; idx += 128){
            const int i = idx / 96, d = idx - 96*i;
            float o = 0.f;
            #pragma unroll
            for (int j = 0; j < 16; j++) o += ps[i][j] * vs[j][d];
            float v = vst[idx];
            v += (o - v)*0.5f;
            const float sp = (v >= 0.5f) ? 1.f : 0.f;
            osp[(size_t)(rowbase + n0 + i)*CDIM + hh*DHEAD + d] = __float2half(sp);
            vst[idx] = v * (1.f - sp);
        }
        __syncthreads();
    }
}

// ---------------- launch ----------------
extern "C" void kernel_launch(void* const* d_in, const int* in_sizes, int n_in,
                              void* d_out, int out_size)
{
    const float* x = (const float*)d_in[0];
    const float* W[6]  = {(const float*)d_in[1],(const float*)d_in[5],(const float*)d_in[9],
                          (const float*)d_in[13],(const float*)d_in[17],(const float*)d_in[21]};
    const float* Bb[6] = {(const float*)d_in[2],(const float*)d_in[6],(const float*)d_in[10],
                          (const float*)d_in[14],(const float*)d_in[18],(const float*)d_in[22]};
    const float* Sc[6] = {(const float*)d_in[3],(const float*)d_in[7],(const float*)d_in[11],
                          (const float*)d_in[15],(const float*)d_in[19],(const float*)d_in[23]};
    const float* Sh[6] = {(const float*)d_in[4],(const float*)d_in[8],(const float*)d_in[12],
                          (const float*)d_in[16],(const float*)d_in[20],(const float*)d_in[24]};

    void *py,*pxs0,*pxs1,*px1s0,*px1s1,*px1f,*pqkv,*posp,*phs,*pw0,*pw1;
    cudaGetSymbolAddress(&py, g_y);
    cudaGetSymbolAddress(&pxs0, g_xs0); cudaGetSymbolAddress(&pxs1, g_xs1);
    cudaGetSymbolAddress(&px1s0, g_x1s0); cudaGetSymbolAddress(&px1s1, g_x1s1);
    cudaGetSymbolAddress(&px1f, g_x1f);
    cudaGetSymbolAddress(&pqkv, g_qkvs); cudaGetSymbolAddress(&posp, g_osp);
    cudaGetSymbolAddress(&phs, g_hs);
    cudaGetSymbolAddress(&pw0, g_w0); cudaGetSymbolAddress(&pw1, g_w1);

    __half* w0 = (__half*)pw0;
    __half* w1 = (__half*)pw1;

    cudaFuncSetAttribute(gemm_mma, cudaFuncAttributeMaxDynamicSharedMemorySize, GSMEM);

    const struct { int wi; size_t off; long long n; } WS[6] = {
        {0, WO_QKV,           (long long)CDIM*CDIM},
        {1, WO_QKV + 589824,  (long long)CDIM*CDIM},
        {2, WO_QKV + 1179648, (long long)CDIM*CDIM},
        {3, WO_P,             (long long)CDIM*CDIM},
        {4, WO_F1,            (long long)HDIM*CDIM},
        {5, WO_F2,            (long long)CDIM*HDIM}};
    for (int i = 0; i < 6; i++){
        const long long n4 = WS[i].n / 4;
        split2_kernel<<<(int)((n4+255)/256), 256>>>(W[WS[i].wi],
            w0 + WS[i].off, w1 + WS[i].off, n4);
    }
    {
        const long long n4 = (long long)MTOT * CDIM / 4;
        split2_kernel<<<(int)((n4+255)/256), 256>>>(x, (__half*)pxs0, (__half*)pxs1, n4);
    }

    GemmP g;
    // qkv: y = a0*w0 + a1*w0 + a0*w1
    g.A[0]=(__half*)pxs0; g.A[1]=(__half*)pxs1; g.A[2]=(__half*)pxs0;
    g.B[0]=w0+WO_QKV;     g.B[1]=w0+WO_QKV;    g.B[2]=w1+WO_QKV;
    g.nseg=3; g.K=CDIM; g.Y=(float*)py; g.N=QKVC;
    gemm_mma<<<dim3(QKVC/128, MTOT/128), 256, GSMEM>>>(g);

    const long long nC = (long long)BNALL*CDIM;
    const int nbC = (int)((nC+255)/256);
    lif_plain<<<nbC,256>>>((float*)py, Bb[0],Sc[0],Sh[0], (__half*)pqkv, CDIM, QKVC, 0,    QKVC, 0);
    lif_plain<<<nbC,256>>>((float*)py, Bb[1],Sc[1],Sh[1], (__half*)pqkv, CDIM, QKVC, 768,  QKVC, 768);
    lif_plain<<<nbC,256>>>((float*)py, Bb[2],Sc[2],Sh[2], (__half*)pqkv, CDIM, QKVC, 1536, QKVC, 1536);

    attn_kernel<<<BATCH*NHEAD*NWIN, 128>>>((const __half*)pqkv, (__half*)posp);

    // proj: spikes exact -> 2 weight segs
    g.A[0]=g.A[1]=(__half*)posp;
    g.B[0]=w0+WO_P; g.B[1]=w1+WO_P;
    g.nseg=2; g.K=CDIM; g.Y=(float*)py; g.N=CDIM;
    gemm_mma<<<dim3(CDIM/128, MTOT/128), 256, GSMEM>>>(g);

    lif_proj<<<nbC,256>>>((float*)py, Bb[3],Sc[3],Sh[3], x, (float*)px1f,
                          (__half*)px1s0, (__half*)px1s1);

    // f1: y = a0*w0 + a1*w0 + a0*w1
    g.A[0]=(__half*)px1s0; g.A[1]=(__half*)px1s1; g.A[2]=(__half*)px1s0;
    g.B[0]=w0+WO_F1;       g.B[1]=w0+WO_F1;      g.B[2]=w1+WO_F1;
    g.nseg=3; g.K=CDIM; g.Y=(float*)py; g.N=HDIM;
    gemm_mma<<<dim3(HDIM/128, MTOT/128), 256, GSMEM>>>(g);

    const long long nH = (long long)BNALL*HDIM;
    lif_plain<<<(int)((nH+255)/256),256>>>((float*)py, Bb[4],Sc[4],Sh[4],
                                           (__half*)phs, HDIM, HDIM, 0, HDIM, 0);

    // f2: spikes exact -> 2 weight segs
    g.A[0]=g.A[1]=(__half*)phs;
    g.B[0]=w0+WO_F2; g.B[1]=w1+WO_F2;
    g.nseg=2; g.K=HDIM; g.Y=(float*)py; g.N=CDIM;
    gemm_mma<<<dim3(CDIM/128, MTOT/128), 256, GSMEM>>>(g);

    lif_out<<<nbC,256>>>((float*)py, Bb[5],Sc[5],Sh[5], (float*)px1f, (float*)d_out);
}